// round 3
// baseline (speedup 1.0000x reference)
#include <cuda_runtime.h>
#include <cuda_fp16.h>
#include <cstdint>
#include <cstddef>

#define BB 2
#define QQ 512
#define KK 512
#define TT 256

// ---------------- scratch (device globals; no allocation) ----------------
__device__ __half g_z[(size_t)BB * KK * TT * QQ];   // [b][i][u][j]  256 MB
__device__ float  g_kproj[BB * KK * TT];            // k projection (fp32)
__device__ __half g_qh[BB * QQ * TT];               // q projection (fp16)
__device__ float  g_v[BB * KK * TT];                // v projection (fp32)
__device__ float  g_w[BB * KK * TT];                // v / (sum|z| + e^m)
__device__ float  g_opre[BB * QQ * TT];             // pre-Wvo output

#define DINL __device__ __forceinline__

DINL uint32_t smem_u32(const void* p) {
    uint32_t a;
    asm("{ .reg .u64 t; cvta.to.shared.u64 t, %1; cvt.u32.u64 %0, t; }" : "=r"(a) : "l"(p));
    return a;
}

DINL void ldsm4(uint32_t& r0, uint32_t& r1, uint32_t& r2, uint32_t& r3, uint32_t addr) {
    asm volatile("ldmatrix.sync.aligned.m8n8.x4.shared.b16 {%0,%1,%2,%3}, [%4];"
                 : "=r"(r0), "=r"(r1), "=r"(r2), "=r"(r3) : "r"(addr));
}

DINL void mma16816(float* c, const uint32_t* a, const uint32_t* b) {
    asm volatile(
        "mma.sync.aligned.m16n8k16.row.col.f32.f16.f16.f32 "
        "{%0,%1,%2,%3}, {%4,%5,%6,%7}, {%8,%9}, {%0,%1,%2,%3};"
        : "+f"(c[0]), "+f"(c[1]), "+f"(c[2]), "+f"(c[3])
        : "r"(a[0]), "r"(a[1]), "r"(a[2]), "r"(a[3]), "r"(b[0]), "r"(b[1]));
}

DINL uint32_t pack2h(float a, float b) {
    __half2 h = __halves2half2(__float2half_rn(a), __float2half_rn(b));
    return *reinterpret_cast<uint32_t*>(&h);
}

// ---------------- projection GEMM: out[r,u] = sum_t X[r,t]*W[u,t] ----------------
__global__ void __launch_bounds__(256) proj_kernel(const float* __restrict__ X,
                                                   const float* __restrict__ W,
                                                   int mode, float* __restrict__ out_ext) {
    __shared__ float xs[32][33];
    __shared__ float ws[64][33];
    const float* Xp = (mode == 3) ? g_opre : X;
    int rb = blockIdx.x * 32, ub = blockIdx.y * 64;
    int tid = threadIdx.x;
    int r = tid & 31, u0 = (tid >> 5) * 8;
    float acc[8];
#pragma unroll
    for (int e = 0; e < 8; e++) acc[e] = 0.f;

    for (int t0 = 0; t0 < TT; t0 += 32) {
#pragma unroll
        for (int l = 0; l < 4; l++) {
            int idx = tid + l * 256; int row = idx >> 5, col = idx & 31;
            xs[row][col] = Xp[(rb + row) * TT + t0 + col];
        }
#pragma unroll
        for (int l = 0; l < 8; l++) {
            int idx = tid + l * 256; int row = idx >> 5, col = idx & 31;
            ws[row][col] = W[(ub + row) * TT + t0 + col];
        }
        __syncthreads();
#pragma unroll
        for (int tt = 0; tt < 32; tt++) {
            float xv = xs[r][tt];
#pragma unroll
            for (int e = 0; e < 8; e++) acc[e] += xv * ws[u0 + e][tt];
        }
        __syncthreads();
    }
#pragma unroll
    for (int e = 0; e < 8; e++) {
        int o = (rb + r) * TT + ub + u0 + e;
        if (mode == 0)      g_kproj[o] = acc[e];
        else if (mode == 1) g_qh[o]    = __float2half_rn(acc[e]);
        else if (mode == 2) g_v[o]     = acc[e];
        else                out_ext[o] = acc[e];
    }
}

// ---------------- core kernel ----------------
// SMEM layout (bytes): A_hi 64KB, A_lo 64KB, B 64KB, red 4KB
#define S_AHI 0
#define S_ALO 65536
#define S_B   131072
#define S_RED 196608
#define S_TOTAL 200704

__global__ void __launch_bounds__(256, 1) attn_core(const float* __restrict__ Wal) {
    extern __shared__ char smem[];
    uint32_t sb = smem_u32(smem);
    float2* red = reinterpret_cast<float2*>(smem + S_RED);

    const int tid = threadIdx.x;
    const int lane = tid & 31;
    const int wid = tid >> 5;
    const int warp_m = wid >> 2;   // 0..1
    const int warp_n = wid & 3;    // 0..3

    const int bx = blockIdx.x;
    const int uh = bx & 1;
    const int i  = (bx >> 1) & 511;
    const int b  = bx >> 10;

    // ---- build A_hi / A_lo = fp16 split of Wal[u_half,:] * k_i[:] (swizzled) ----
    const float* __restrict__ walr = Wal + (size_t)uh * 128 * TT;
    const float* __restrict__ kp   = g_kproj + (b * KK + i) * TT;
#pragma unroll
    for (int it = 0; it < 16; it++) {
        int idx = tid + it * 256;
        int row = idx >> 5, cc = idx & 31;
        int t0 = cc * 8;
        float4 w0 = *reinterpret_cast<const float4*>(walr + row * TT + t0);
        float4 w1 = *reinterpret_cast<const float4*>(walr + row * TT + t0 + 4);
        float4 k0 = __ldg(reinterpret_cast<const float4*>(kp + t0));
        float4 k1 = __ldg(reinterpret_cast<const float4*>(kp + t0 + 4));
        float a[8] = {w0.x * k0.x, w0.y * k0.y, w0.z * k0.z, w0.w * k0.w,
                      w1.x * k1.x, w1.y * k1.y, w1.z * k1.z, w1.w * k1.w};
        uint4 vh, vl;
        uint32_t* ph = &vh.x;
        uint32_t* pl = &vl.x;
#pragma unroll
        for (int g = 0; g < 4; g++) {
            float f0 = a[g * 2], f1 = a[g * 2 + 1];
            __half e0 = __float2half_rn(f0);
            __half e1 = __float2half_rn(f1);
            __half2 hh = __halves2half2(e0, e1);
            ph[g] = *reinterpret_cast<uint32_t*>(&hh);
            pl[g] = pack2h(f0 - __half2float(e0), f1 - __half2float(e1));
        }
        uint32_t off = (uint32_t)(row * 512 + ((cc ^ (row & 7)) << 4));
        *reinterpret_cast<uint4*>(smem + S_AHI + off) = vh;
        *reinterpret_cast<uint4*>(smem + S_ALO + off) = vl;
    }

    // ---- precompute ldmatrix lane bases ----
    uint32_t cAhi[4], cAlo[4];
    int xA[4];
    const int cbitA = lane >> 4;
#pragma unroll
    for (int f = 0; f < 4; f++) {
        int rowA = warp_m * 64 + f * 16 + (lane & 15);
        cAhi[f] = sb + S_AHI + rowA * 512;
        cAlo[f] = sb + S_ALO + rowA * 512;
        xA[f] = rowA & 7;
    }
    uint32_t cB[2];
    int xB[2];
    const int cbitB = (lane >> 3) & 1;
#pragma unroll
    for (int e = 0; e < 2; e++) {
        int rowB = warp_n * 32 + e * 16 + (lane & 7) + ((lane >> 4) << 3);
        cB[e] = sb + S_B + rowB * 512;
        xB[e] = rowB & 7;
    }

    const __half* __restrict__ qb = g_qh + (size_t)b * QQ * TT;

    float m8[8], s8[8];
#pragma unroll
    for (int e = 0; e < 8; e++) { m8[e] = -3.0e38f; s8[e] = 0.f; }

    const size_t zbase = ((size_t)((b * KK + i) * TT + uh * 128)) * QQ;

    for (int jc = 0; jc < 4; jc++) {
        __syncthreads();   // A ready (jc=0) / previous chunk's B reads done
        // load B chunk [128 j][256 t] fp16, swizzled
#pragma unroll
        for (int it = 0; it < 16; it++) {
            int idx = tid + it * 256;
            int row = idx >> 5, cc = idx & 31;
            uint4 v = *reinterpret_cast<const uint4*>(qb + (size_t)(jc * 128 + row) * TT + cc * 8);
            uint32_t off = (uint32_t)(row * 512 + ((cc ^ (row & 7)) << 4));
            *reinterpret_cast<uint4*>(smem + S_B + off) = v;
        }
        __syncthreads();

        float acc[4][4][4];
#pragma unroll
        for (int f = 0; f < 4; f++)
#pragma unroll
            for (int g = 0; g < 4; g++)
#pragma unroll
                for (int c = 0; c < 4; c++) acc[f][g][c] = 0.f;

#pragma unroll
        for (int ks = 0; ks < 16; ks++) {
            uint32_t bfr[8];
            ldsm4(bfr[0], bfr[1], bfr[2], bfr[3],
                  cB[0] + (uint32_t)(((2 * ks + cbitB) ^ xB[0]) << 4));
            ldsm4(bfr[4], bfr[5], bfr[6], bfr[7],
                  cB[1] + (uint32_t)(((2 * ks + cbitB) ^ xB[1]) << 4));

            uint32_t ah[16];
#pragma unroll
            for (int f = 0; f < 4; f++)
                ldsm4(ah[4 * f], ah[4 * f + 1], ah[4 * f + 2], ah[4 * f + 3],
                      cAhi[f] + (uint32_t)(((2 * ks + cbitA) ^ xA[f]) << 4));
#pragma unroll
            for (int f = 0; f < 4; f++)
#pragma unroll
                for (int g = 0; g < 4; g++)
                    mma16816(acc[f][g], &ah[4 * f], &bfr[2 * g]);

            uint32_t al[16];
#pragma unroll
            for (int f = 0; f < 4; f++)
                ldsm4(al[4 * f], al[4 * f + 1], al[4 * f + 2], al[4 * f + 3],
                      cAlo[f] + (uint32_t)(((2 * ks + cbitA) ^ xA[f]) << 4));
#pragma unroll
            for (int f = 0; f < 4; f++)
#pragma unroll
                for (int g = 0; g < 4; g++)
                    mma16816(acc[f][g], &al[4 * f], &bfr[2 * g]);
        }

        // ---- epilogue: z = l*e^l, fp16 store, running (max, sum|z|) ----
#pragma unroll
        for (int f = 0; f < 4; f++) {
#pragma unroll
            for (int h = 0; h < 2; h++) {
                int u_local = warp_m * 64 + f * 16 + h * 8 + (lane >> 2);
                __half* zr = g_z + zbase + (size_t)u_local * QQ
                             + jc * 128 + warp_n * 32 + (lane & 3) * 2;
                float mv = m8[f * 2 + h], sv = s8[f * 2 + h];
#pragma unroll
                for (int g = 0; g < 4; g++) {
                    float l0 = acc[f][g][h * 2 + 0];
                    float l1 = acc[f][g][h * 2 + 1];
                    float z0 = l0 * __expf(l0);
                    float z1 = l1 * __expf(l1);
                    mv = fmaxf(mv, fmaxf(l0, l1));
                    sv += fabsf(z0) + fabsf(z1);
                    *reinterpret_cast<__half2*>(zr + g * 8) =
                        __halves2half2(__float2half_rn(z0), __float2half_rn(z1));
                }
                m8[f * 2 + h] = mv;
                s8[f * 2 + h] = sv;
            }
        }
    }

    // ---- reduce (m, s) over j: quad shuffle, then across n-warps via smem ----
#pragma unroll
    for (int e = 0; e < 8; e++) {
#pragma unroll
        for (int off = 1; off <= 2; off <<= 1) {
            m8[e] = fmaxf(m8[e], __shfl_xor_sync(0xFFFFFFFFu, m8[e], off));
            s8[e] += __shfl_xor_sync(0xFFFFFFFFu, s8[e], off);
        }
    }
    __syncthreads();  // red region: no other use, but order vs nothing — safe
    if ((lane & 3) == 0) {
#pragma unroll
        for (int f = 0; f < 4; f++)
#pragma unroll
            for (int h = 0; h < 2; h++) {
                int u_local = warp_m * 64 + f * 16 + h * 8 + (lane >> 2);
                red[warp_n * 128 + u_local] = make_float2(m8[f * 2 + h], s8[f * 2 + h]);
            }
    }
    __syncthreads();
    if (tid < 128) {
        float mv = -3.0e38f, sv = 0.f;
#pragma unroll
        for (int wn = 0; wn < 4; wn++) {
            float2 p = red[wn * 128 + tid];
            mv = fmaxf(mv, p.x);
            sv += p.y;
        }
        int u = uh * 128 + tid;
        int vi = (b * KK + i) * TT + u;
        g_w[vi] = g_v[vi] / (sv + __expf(mv));
    }
}

// ---------------- combine: out_pre[b,j,u] = sum_i w[b,i,u] * z[b,i,u,j] ----------------
__global__ void __launch_bounds__(256) combine_kernel() {
    int u = blockIdx.x, b = blockIdx.y;
    int tid = threadIdx.x;
    const __half2* zp = reinterpret_cast<const __half2*>(g_z);
    float accx = 0.f, accy = 0.f;
    int base_iu = b * KK * TT + u;
#pragma unroll 4
    for (int i = 0; i < KK; i++) {
        int iu = base_iu + i * TT;
        float wv = g_w[iu];
        __half2 zz = zp[(size_t)iu * (QQ / 2) + tid];
        float2 zf = __half22float2(zz);
        accx += wv * zf.x;
        accy += wv * zf.y;
    }
    int j = tid * 2;
    g_opre[(b * QQ + j) * TT + u]     = accx;
    g_opre[(b * QQ + j + 1) * TT + u] = accy;
}

// ---------------- launch ----------------
extern "C" void kernel_launch(void* const* d_in, const int* in_sizes, int n_in,
                              void* d_out, int out_size) {
    const float* q_t = (const float*)d_in[0];
    const float* k_t = (const float*)d_in[1];
    const float* v_t = (const float*)d_in[2];
    const float* Wk  = (const float*)d_in[3];
    const float* Wq  = (const float*)d_in[4];
    const float* Wva = (const float*)d_in[5];
    const float* Wal = (const float*)d_in[6];
    const float* Wvo = (const float*)d_in[7];
    float* out = (float*)d_out;

    cudaFuncSetAttribute(attn_core, cudaFuncAttributeMaxDynamicSharedMemorySize, S_TOTAL);

    dim3 pg(32, 4);
    proj_kernel<<<pg, 256>>>(k_t, Wk, 0, nullptr);   // g_kproj
    proj_kernel<<<pg, 256>>>(q_t, Wq, 1, nullptr);   // g_qh
    proj_kernel<<<pg, 256>>>(v_t, Wva, 2, nullptr);  // g_v

    attn_core<<<BB * KK * 2, 256, S_TOTAL>>>(Wal);

    combine_kernel<<<dim3(TT, BB), 256>>>();

    proj_kernel<<<pg, 256>>>(nullptr, Wvo, 3, out);  // out = g_opre @ Wvo^T
}

// round 4
// speedup vs baseline: 1.0549x; 1.0549x over previous
#include <cuda_runtime.h>
#include <cuda_fp16.h>
#include <cstdint>
#include <cstddef>

#define BB 2
#define QQ 512
#define KK 512
#define TT 256

// ---------------- scratch (device globals; no allocation) ----------------
__device__ __half g_z[(size_t)BB * KK * TT * QQ];   // [b][i][u][j]  256 MB
__device__ float  g_kproj[BB * KK * TT];            // k projection (fp32)
__device__ __half g_qh[BB * QQ * TT];               // q projection (fp16)
__device__ float  g_v[BB * KK * TT];                // v projection (fp32)
__device__ float  g_w[BB * KK * TT];                // v / (sum|z| + e^m)
__device__ float  g_opre[BB * QQ * TT];             // pre-Wvo output

#define DINL __device__ __forceinline__

DINL uint32_t smem_u32(const void* p) {
    uint32_t a;
    asm("{ .reg .u64 t; cvta.to.shared.u64 t, %1; cvt.u32.u64 %0, t; }" : "=r"(a) : "l"(p));
    return a;
}

DINL void ldsm4(uint32_t& r0, uint32_t& r1, uint32_t& r2, uint32_t& r3, uint32_t addr) {
    asm volatile("ldmatrix.sync.aligned.m8n8.x4.shared.b16 {%0,%1,%2,%3}, [%4];"
                 : "=r"(r0), "=r"(r1), "=r"(r2), "=r"(r3) : "r"(addr));
}

DINL void mma16816(float* c, const uint32_t* a, const uint32_t* b) {
    asm volatile(
        "mma.sync.aligned.m16n8k16.row.col.f32.f16.f16.f32 "
        "{%0,%1,%2,%3}, {%4,%5,%6,%7}, {%8,%9}, {%0,%1,%2,%3};"
        : "+f"(c[0]), "+f"(c[1]), "+f"(c[2]), "+f"(c[3])
        : "r"(a[0]), "r"(a[1]), "r"(a[2]), "r"(a[3]), "r"(b[0]), "r"(b[1]));
}

// f16-accumulator variant for the lo pass (acc values are tiny corrections)
DINL void mma16816_f16(uint32_t* c, const uint32_t* a, const uint32_t* b) {
    asm volatile(
        "mma.sync.aligned.m16n8k16.row.col.f16.f16.f16.f16 "
        "{%0,%1}, {%2,%3,%4,%5}, {%6,%7}, {%0,%1};"
        : "+r"(c[0]), "+r"(c[1])
        : "r"(a[0]), "r"(a[1]), "r"(a[2]), "r"(a[3]), "r"(b[0]), "r"(b[1]));
}

DINL void cp_async16(uint32_t smem_addr, const void* gptr) {
    asm volatile("cp.async.ca.shared.global [%0], [%1], 16;"
                 :: "r"(smem_addr), "l"(gptr) : "memory");
}
DINL void cp_commit() { asm volatile("cp.async.commit_group;" ::: "memory"); }
template <int N> DINL void cp_wait() {
    asm volatile("cp.async.wait_group %0;" :: "n"(N) : "memory");
}

DINL uint32_t pack2h(float a, float b) {
    __half2 h = __halves2half2(__float2half_rn(a), __float2half_rn(b));
    return *reinterpret_cast<uint32_t*>(&h);
}

// ---------------- projection GEMM: out[r,u] = sum_t X[r,t]*W[u,t] ----------------
__global__ void __launch_bounds__(256) proj_kernel(const float* __restrict__ X,
                                                   const float* __restrict__ W,
                                                   int mode, float* __restrict__ out_ext) {
    __shared__ float xs[32][33];
    __shared__ float ws[64][33];
    const float* Xp = (mode == 3) ? g_opre : X;
    int rb = blockIdx.x * 32, ub = blockIdx.y * 64;
    int tid = threadIdx.x;
    int r = tid & 31, u0 = (tid >> 5) * 8;
    float acc[8];
#pragma unroll
    for (int e = 0; e < 8; e++) acc[e] = 0.f;

    for (int t0 = 0; t0 < TT; t0 += 32) {
#pragma unroll
        for (int l = 0; l < 4; l++) {
            int idx = tid + l * 256; int row = idx >> 5, col = idx & 31;
            xs[row][col] = Xp[(rb + row) * TT + t0 + col];
        }
#pragma unroll
        for (int l = 0; l < 8; l++) {
            int idx = tid + l * 256; int row = idx >> 5, col = idx & 31;
            ws[row][col] = W[(ub + row) * TT + t0 + col];
        }
        __syncthreads();
#pragma unroll
        for (int tt = 0; tt < 32; tt++) {
            float xv = xs[r][tt];
#pragma unroll
            for (int e = 0; e < 8; e++) acc[e] += xv * ws[u0 + e][tt];
        }
        __syncthreads();
    }
#pragma unroll
    for (int e = 0; e < 8; e++) {
        int o = (rb + r) * TT + ub + u0 + e;
        if (mode == 0)      g_kproj[o] = acc[e];
        else if (mode == 1) g_qh[o]    = __float2half_rn(acc[e]);
        else if (mode == 2) g_v[o]     = acc[e];
        else                out_ext[o] = acc[e];
    }
}

// ---------------- core kernel ----------------
// SMEM: A staging reuses the same 64KB region as the two 32KB B buffers.
#define S_B0 0
#define S_B1 32768
#define S_TOTAL 65536

DINL void copy_b_chunk(uint32_t sdst, const __half* __restrict__ gsrc, int tid) {
#pragma unroll
    for (int it = 0; it < 8; it++) {
        int idx = tid + it * 256;
        int row = idx >> 5, cc = idx & 31;
        uint32_t off = (uint32_t)(row * 512 + ((cc ^ (row & 7)) << 4));
        cp_async16(sdst + off, gsrc + (size_t)row * TT + cc * 8);
    }
}

__global__ void __launch_bounds__(256, 1) attn_core(const float* __restrict__ Wal) {
    extern __shared__ char smem[];
    uint32_t sb = smem_u32(smem);
    const int tid = threadIdx.x;
    const int lane = tid & 31;
    const int wid = tid >> 5;

    const int bx = blockIdx.x;
    const int uh = bx & 1;
    const int i  = (bx >> 1) & 511;
    const int b  = bx >> 10;

    const float* __restrict__ walr = Wal + (size_t)uh * 128 * TT;
    const float* __restrict__ kp   = g_kproj + (b * KK + i) * TT;

    // A ldmatrix lane addressing (each warp owns u-rows [wid*16, wid*16+16))
    const int rowA = wid * 16 + (lane & 15);
    const uint32_t aBase = sb + (uint32_t)rowA * 512;
    const int xA = rowA & 7;
    const int cbitA = lane >> 4;

    uint32_t ahi[64], alo[64];   // A fragments, resident in registers for the whole CTA

    // ---- stage A_hi then A_lo through the (to-be) B buffer region ----
#pragma unroll 1
    for (int pass = 0; pass < 2; pass++) {
#pragma unroll
        for (int it = 0; it < 16; it++) {
            int idx = tid + it * 256;
            int row = idx >> 5, cc = idx & 31;
            int t0 = cc * 8;
            float4 w0 = *reinterpret_cast<const float4*>(walr + row * TT + t0);
            float4 w1 = *reinterpret_cast<const float4*>(walr + row * TT + t0 + 4);
            float4 k0 = __ldg(reinterpret_cast<const float4*>(kp + t0));
            float4 k1 = __ldg(reinterpret_cast<const float4*>(kp + t0 + 4));
            float a[8] = {w0.x * k0.x, w0.y * k0.y, w0.z * k0.z, w0.w * k0.w,
                          w1.x * k1.x, w1.y * k1.y, w1.z * k1.z, w1.w * k1.w};
            uint4 v;
            uint32_t* pv = &v.x;
#pragma unroll
            for (int g = 0; g < 4; g++) {
                float f0 = a[g * 2], f1 = a[g * 2 + 1];
                if (pass == 0) {
                    pv[g] = pack2h(f0, f1);
                } else {
                    __half e0 = __float2half_rn(f0);
                    __half e1 = __float2half_rn(f1);
                    pv[g] = pack2h(f0 - __half2float(e0), f1 - __half2float(e1));
                }
            }
            uint32_t off = (uint32_t)(row * 512 + ((cc ^ (row & 7)) << 4));
            *reinterpret_cast<uint4*>(smem + off) = v;
        }
        __syncthreads();
        uint32_t* dst = (pass == 0) ? ahi : alo;
#pragma unroll
        for (int ks = 0; ks < 16; ks++) {
            ldsm4(dst[ks * 4], dst[ks * 4 + 1], dst[ks * 4 + 2], dst[ks * 4 + 3],
                  aBase + (uint32_t)(((2 * ks + cbitA) ^ xA) << 4));
        }
        __syncthreads();
    }

    // B ldmatrix lane addressing (all warps read the same 64-j chunk)
    uint32_t bBase[4]; int xB[4];
    const int cbitB = (lane >> 3) & 1;
#pragma unroll
    for (int e = 0; e < 4; e++) {
        int rowB = e * 16 + (lane & 7) + ((lane >> 4) << 3);
        bBase[e] = (uint32_t)(rowB * 512);
        xB[e] = rowB & 7;
    }

    const __half* __restrict__ qb = g_qh + (size_t)b * QQ * TT;
    const size_t zbase = ((size_t)((b * KK + i) * TT + uh * 128)) * QQ;

    float m2[2] = {-3.0e38f, -3.0e38f};
    float s2[2] = {0.f, 0.f};

    // prologue: start copying chunk 0
    copy_b_chunk(sb + S_B0, qb, tid);
    cp_commit();

    for (int c = 0; c < 8; c++) {
        __syncthreads();   // all warps done reading buffer about to be overwritten
        if (c < 7) {
            copy_b_chunk(sb + (((c + 1) & 1) ? S_B1 : S_B0),
                         qb + (size_t)(c + 1) * 64 * TT, tid);
            cp_commit();
            cp_wait<1>();  // chunk c landed (newest group still in flight)
        } else {
            cp_wait<0>();
        }
        __syncthreads();
        const uint32_t bb = sb + ((c & 1) ? S_B1 : S_B0);

        float acc[8][4];
        uint32_t accl[8][2];
#pragma unroll
        for (int g = 0; g < 8; g++) {
#pragma unroll
            for (int x = 0; x < 4; x++) acc[g][x] = 0.f;
            accl[g][0] = 0u; accl[g][1] = 0u;
        }

#pragma unroll
        for (int ks = 0; ks < 16; ks++) {
            uint32_t bfr[16];
#pragma unroll
            for (int e = 0; e < 4; e++)
                ldsm4(bfr[e * 4], bfr[e * 4 + 1], bfr[e * 4 + 2], bfr[e * 4 + 3],
                      bb + bBase[e] + (uint32_t)(((2 * ks + cbitB) ^ xB[e]) << 4));
#pragma unroll
            for (int g = 0; g < 8; g++)
                mma16816(acc[g], &ahi[ks * 4], &bfr[2 * g]);
#pragma unroll
            for (int g = 0; g < 8; g++)
                mma16816_f16(accl[g], &alo[ks * 4], &bfr[2 * g]);
        }

        // ---- epilogue: l = hi + lo; z = l*e^l; fp16 streaming store; (m,s) ----
#pragma unroll
        for (int h = 0; h < 2; h++) {
            int u_local = wid * 16 + h * 8 + (lane >> 2);
            __half* zr = g_z + zbase + (size_t)u_local * QQ + c * 64 + (lane & 3) * 2;
            float mv = m2[h], sv = s2[h];
#pragma unroll
            for (int g = 0; g < 8; g++) {
                float2 lo = __half22float2(*reinterpret_cast<__half2*>(&accl[g][h]));
                float l0 = acc[g][h * 2 + 0] + lo.x;
                float l1 = acc[g][h * 2 + 1] + lo.y;
                float z0 = l0 * __expf(l0);
                float z1 = l1 * __expf(l1);
                mv = fmaxf(mv, fmaxf(l0, l1));
                sv += fabsf(z0) + fabsf(z1);
                __stcs(reinterpret_cast<__half2*>(zr + g * 8),
                       __halves2half2(__float2half_rn(z0), __float2half_rn(z1)));
            }
            m2[h] = mv; s2[h] = sv;
        }
    }

    // ---- (m,s) complete within the warp: quad shuffle, write w directly ----
#pragma unroll
    for (int h = 0; h < 2; h++) {
#pragma unroll
        for (int off = 1; off <= 2; off <<= 1) {
            m2[h] = fmaxf(m2[h], __shfl_xor_sync(0xFFFFFFFFu, m2[h], off));
            s2[h] += __shfl_xor_sync(0xFFFFFFFFu, s2[h], off);
        }
        if ((lane & 3) == 0) {
            int u = uh * 128 + wid * 16 + h * 8 + (lane >> 2);
            int vi = (b * KK + i) * TT + u;
            g_w[vi] = g_v[vi] / (s2[h] + __expf(m2[h]));
        }
    }
}

// ---------------- combine: out_pre[b,j,u] = sum_i w[b,i,u] * z[b,i,u,j] ----------------
__global__ void __launch_bounds__(256) combine_kernel() {
    __shared__ float ws[KK];
    int u = blockIdx.x, b = blockIdx.y;
    int tid = threadIdx.x;
    for (int ii = tid; ii < KK; ii += 256)
        ws[ii] = g_w[(b * KK + ii) * TT + u];
    __syncthreads();

    const __half2* zp = reinterpret_cast<const __half2*>(g_z)
                        + ((size_t)(b * KK * TT + u)) * (QQ / 2) + tid;
    float accx = 0.f, accy = 0.f;
#pragma unroll 8
    for (int i = 0; i < KK; i++) {
        __half2 zz = __ldcs(zp);
        float2 zf = __half22float2(zz);
        float wv = ws[i];
        accx += wv * zf.x;
        accy += wv * zf.y;
        zp += (size_t)TT * (QQ / 2);
    }
    int j = tid * 2;
    g_opre[(b * QQ + j) * TT + u]     = accx;
    g_opre[(b * QQ + j + 1) * TT + u] = accy;
}

// ---------------- launch ----------------
extern "C" void kernel_launch(void* const* d_in, const int* in_sizes, int n_in,
                              void* d_out, int out_size) {
    const float* q_t = (const float*)d_in[0];
    const float* k_t = (const float*)d_in[1];
    const float* v_t = (const float*)d_in[2];
    const float* Wk  = (const float*)d_in[3];
    const float* Wq  = (const float*)d_in[4];
    const float* Wva = (const float*)d_in[5];
    const float* Wal = (const float*)d_in[6];
    const float* Wvo = (const float*)d_in[7];
    float* out = (float*)d_out;

    cudaFuncSetAttribute(attn_core, cudaFuncAttributeMaxDynamicSharedMemorySize, S_TOTAL);

    dim3 pg(32, 4);
    proj_kernel<<<pg, 256>>>(k_t, Wk, 0, nullptr);   // g_kproj
    proj_kernel<<<pg, 256>>>(q_t, Wq, 1, nullptr);   // g_qh
    proj_kernel<<<pg, 256>>>(v_t, Wva, 2, nullptr);  // g_v

    attn_core<<<BB * KK * 2, 256, S_TOTAL>>>(Wal);

    combine_kernel<<<dim3(TT, BB), 256>>>();

    proj_kernel<<<pg, 256>>>(nullptr, Wvo, 3, out);  // out = g_opre @ Wvo^T
}

// round 6
// speedup vs baseline: 1.6247x; 1.5401x over previous
#include <cuda_runtime.h>
#include <cuda_fp16.h>
#include <cstdint>
#include <cstddef>

#define BB 2
#define QQ 512
#define KK 512
#define TT 256

// ---------------- scratch (device globals; no allocation) ----------------
__device__ __half g_z[(size_t)BB * KK * TT * QQ];   // [b][i][u][j]  256 MB
__device__ float  g_kproj[BB * KK * TT];            // k projection (fp32)
__device__ __half g_qh[BB * QQ * TT];               // q projection, PRE-SWIZZLED chunk layout
__device__ float  g_v[BB * KK * TT];                // v projection (fp32)
__device__ float  g_w[BB * KK * TT];                // v / (sum|z| + e^m)
__device__ float  g_opre[BB * QQ * TT];             // pre-Wvo output

#define DINL __device__ __forceinline__

DINL uint32_t smem_u32(const void* p) {
    uint32_t a;
    asm("{ .reg .u64 t; cvta.to.shared.u64 t, %1; cvt.u32.u64 %0, t; }" : "=r"(a) : "l"(p));
    return a;
}

DINL void ldsm4(uint32_t& r0, uint32_t& r1, uint32_t& r2, uint32_t& r3, uint32_t addr) {
    asm volatile("ldmatrix.sync.aligned.m8n8.x4.shared.b16 {%0,%1,%2,%3}, [%4];"
                 : "=r"(r0), "=r"(r1), "=r"(r2), "=r"(r3) : "r"(addr));
}

DINL void mma16816(float* c, const uint32_t* a, const uint32_t* b) {
    asm volatile(
        "mma.sync.aligned.m16n8k16.row.col.f32.f16.f16.f32 "
        "{%0,%1,%2,%3}, {%4,%5,%6,%7}, {%8,%9}, {%0,%1,%2,%3};"
        : "+f"(c[0]), "+f"(c[1]), "+f"(c[2]), "+f"(c[3])
        : "r"(a[0]), "r"(a[1]), "r"(a[2]), "r"(a[3]), "r"(b[0]), "r"(b[1]));
}

// ---- sm_90 bulk-copy + mbarrier (plain compute_103-legal PTX) ----
DINL void mbar_init(uint32_t mbar, uint32_t cnt) {
    asm volatile("mbarrier.init.shared.b64 [%0], %1;" :: "r"(mbar), "r"(cnt) : "memory");
}
DINL void mbar_expect_tx(uint32_t mbar, uint32_t bytes) {
    asm volatile("mbarrier.arrive.expect_tx.shared.b64 _, [%0], %1;"
                 :: "r"(mbar), "r"(bytes) : "memory");
}
DINL void bulk_copy_g2s(uint32_t sdst, const void* gsrc, uint32_t bytes, uint32_t mbar) {
    asm volatile(
        "cp.async.bulk.shared::cluster.global.mbarrier::complete_tx::bytes [%0], [%1], %2, [%3];"
        :: "r"(sdst), "l"(gsrc), "r"(bytes), "r"(mbar) : "memory");
}
DINL void mbar_wait(uint32_t mbar, uint32_t parity) {
    asm volatile(
        "{\n\t.reg .pred P;\n\tW%=:\n\t"
        "mbarrier.try_wait.parity.shared::cta.b64 P, [%0], %1, 0x989680;\n\t"
        "@!P bra.uni W%=;\n\t}"
        :: "r"(mbar), "r"(parity) : "memory");
}
DINL void fence_async() { asm volatile("fence.proxy.async.shared::cta;" ::: "memory"); }

DINL uint32_t pack2h(float a, float b) {
    __half2 h = __halves2half2(__float2half_rn(a), __float2half_rn(b));
    return *reinterpret_cast<uint32_t*>(&h);
}

// ---------------- projection GEMM: out[r,u] = sum_t X[r,t]*W[u,t] ----------------
__global__ void __launch_bounds__(256) proj_kernel(const float* __restrict__ X,
                                                   const float* __restrict__ W,
                                                   int mode, float* __restrict__ out_ext) {
    __shared__ float xs[32][33];
    __shared__ float ws[64][33];
    const float* Xp = (mode == 3) ? g_opre : X;
    int rb = blockIdx.x * 32, ub = blockIdx.y * 64;
    int tid = threadIdx.x;
    int r = tid & 31, u0 = (tid >> 5) * 8;
    float acc[8];
#pragma unroll
    for (int e = 0; e < 8; e++) acc[e] = 0.f;

    for (int t0 = 0; t0 < TT; t0 += 32) {
#pragma unroll
        for (int l = 0; l < 4; l++) {
            int idx = tid + l * 256; int row = idx >> 5, col = idx & 31;
            xs[row][col] = Xp[(rb + row) * TT + t0 + col];
        }
#pragma unroll
        for (int l = 0; l < 8; l++) {
            int idx = tid + l * 256; int row = idx >> 5, col = idx & 31;
            ws[row][col] = W[(ub + row) * TT + t0 + col];
        }
        __syncthreads();
#pragma unroll
        for (int tt = 0; tt < 32; tt++) {
            float xv = xs[r][tt];
#pragma unroll
            for (int e = 0; e < 8; e++) acc[e] += xv * ws[u0 + e][tt];
        }
        __syncthreads();
    }
    if (mode == 1) {
        // q projection -> PRE-SWIZZLED chunk layout:
        // half index = ((b*8 + jchunk)*64 + rr)*256 + ((grp ^ (rr&7))*8 + t%8)
        int rg = rb + r;
        int bb2 = rg >> 9, j = rg & 511;
        int cch = j >> 6, rr = j & 63;
        int grp = (ub + u0) >> 3;
        uint32_t hoff = ((uint32_t)((bb2 * 8 + cch) * 64 + rr)) * 256u
                        + (uint32_t)((grp ^ (rr & 7)) << 3);
        uint4 v;
        v.x = pack2h(acc[0], acc[1]);
        v.y = pack2h(acc[2], acc[3]);
        v.z = pack2h(acc[4], acc[5]);
        v.w = pack2h(acc[6], acc[7]);
        *reinterpret_cast<uint4*>(g_qh + hoff) = v;
    } else {
#pragma unroll
        for (int e = 0; e < 8; e++) {
            int o = (rb + r) * TT + ub + u0 + e;
            if (mode == 0)      g_kproj[o] = acc[e];
            else if (mode == 2) g_v[o]     = acc[e];
            else                out_ext[o] = acc[e];
        }
    }
}

// ---------------- core kernel ----------------
#define S_B0 0
#define S_B1 32768
#define S_MB 65536
#define S_TOTAL 65552
#define CHUNK_BYTES 32768u

__global__ void __launch_bounds__(512, 1) attn_core(const float* __restrict__ Wal) {
    extern __shared__ char smem[];
    uint32_t sb = smem_u32(smem);
    const int tid = threadIdx.x;
    const int lane = tid & 31;
    const int wid = tid >> 5;
    const int warp_m = wid >> 1;   // 0..7  (16 u-rows each)
    const int warp_n = wid & 1;    // 0..1  (32 j-cols each)

    const int bx = blockIdx.x;
    const int uh = bx & 1;
    const int i  = (bx >> 1) & 511;
    const int b  = bx >> 10;

    const uint32_t mb0 = sb + S_MB, mb1 = sb + S_MB + 8;

    // ---- init mbarriers FIRST (published to all threads by the syncthreads below) ----
    if (tid == 0) {
        mbar_init(mb0, 1);
        mbar_init(mb1, 1);
        fence_async();
    }

    const float* __restrict__ walr = Wal + (size_t)uh * 128 * TT;
    const float* __restrict__ kp   = g_kproj + (b * KK + i) * TT;

    // ---- build A = fp16(Wal[u_half,:] * k_i[:]) staged in smem (64KB slab) ----
#pragma unroll
    for (int it = 0; it < 8; it++) {
        int idx = tid + it * 512;
        int row = idx >> 5, cc = idx & 31;
        int t0 = cc * 8;
        float4 w0 = *reinterpret_cast<const float4*>(walr + row * TT + t0);
        float4 w1 = *reinterpret_cast<const float4*>(walr + row * TT + t0 + 4);
        float4 k0 = __ldg(reinterpret_cast<const float4*>(kp + t0));
        float4 k1 = __ldg(reinterpret_cast<const float4*>(kp + t0 + 4));
        uint4 v;
        v.x = pack2h(w0.x * k0.x, w0.y * k0.y);
        v.y = pack2h(w0.z * k0.z, w0.w * k0.w);
        v.z = pack2h(w1.x * k1.x, w1.y * k1.y);
        v.w = pack2h(w1.z * k1.z, w1.w * k1.w);
        uint32_t off = (uint32_t)(row * 512 + ((cc ^ (row & 7)) << 4));
        *reinterpret_cast<uint4*>(smem + off) = v;
    }
    __syncthreads();   // A staged AND mbarriers initialized

    // A fragments -> registers (warp owns u-rows [warp_m*16, +16))
    const int rowA = warp_m * 16 + (lane & 15);
    const uint32_t aBase = sb + (uint32_t)rowA * 512;
    const int xA = rowA & 7;
    const int cbitA = lane >> 4;
    uint32_t ahi[64];
#pragma unroll
    for (int ks = 0; ks < 16; ks++)
        ldsm4(ahi[ks * 4], ahi[ks * 4 + 1], ahi[ks * 4 + 2], ahi[ks * 4 + 3],
              aBase + (uint32_t)(((2 * ks + cbitA) ^ xA) << 4));
    __syncthreads();   // everyone done reading the A slab; safe to overwrite with B

    // ---- prologue bulk copies (chunks 0 and 1) ----
    const __half* __restrict__ qsw = g_qh + (size_t)(b * 8) * 64 * 256;
    if (tid == 0) {
        mbar_expect_tx(mb0, CHUNK_BYTES);
        bulk_copy_g2s(sb + S_B0, qsw, CHUNK_BYTES, mb0);
        mbar_expect_tx(mb1, CHUNK_BYTES);
        bulk_copy_g2s(sb + S_B1, qsw + 64 * 256, CHUNK_BYTES, mb1);
    }

    // B ldmatrix lane addressing (warp reads j in [warp_n*32, +32))
    uint32_t bBase[2]; int xB[2];
    const int cbitB = (lane >> 3) & 1;
#pragma unroll
    for (int e = 0; e < 2; e++) {
        int rowB = warp_n * 32 + e * 16 + (lane & 7) + ((lane >> 4) << 3);
        bBase[e] = (uint32_t)(rowB * 512);
        xB[e] = rowB & 7;
    }

    const size_t zbase = ((size_t)((b * KK + i) * TT + uh * 128)) * QQ;
    float m2[2] = {-3.0e38f, -3.0e38f};
    float s2[2] = {0.f, 0.f};

    for (int c = 0; c < 8; c++) {
        mbar_wait((c & 1) ? mb1 : mb0, (uint32_t)((c >> 1) & 1));
        const uint32_t bb = sb + ((c & 1) ? S_B1 : S_B0);

        float acc[4][4];
#pragma unroll
        for (int g = 0; g < 4; g++)
#pragma unroll
            for (int x = 0; x < 4; x++) acc[g][x] = 0.f;

#pragma unroll
        for (int ks = 0; ks < 16; ks++) {
            uint32_t bfr[8];
#pragma unroll
            for (int e = 0; e < 2; e++)
                ldsm4(bfr[e * 4], bfr[e * 4 + 1], bfr[e * 4 + 2], bfr[e * 4 + 3],
                      bb + bBase[e] + (uint32_t)(((2 * ks + cbitB) ^ xB[e]) << 4));
#pragma unroll
            for (int g = 0; g < 4; g++)
                mma16816(acc[g], &ahi[ks * 4], &bfr[2 * g]);
        }

        // ---- epilogue: z = l*e^l; fp16 streaming store; running (m, sum|z|) ----
#pragma unroll
        for (int h = 0; h < 2; h++) {
            int u_local = warp_m * 16 + h * 8 + (lane >> 2);
            __half* zr = g_z + zbase + (size_t)u_local * QQ
                         + c * 64 + warp_n * 32 + (lane & 3) * 2;
            float mv = m2[h], sv = s2[h];
#pragma unroll
            for (int g = 0; g < 4; g++) {
                float l0 = acc[g][h * 2 + 0];
                float l1 = acc[g][h * 2 + 1];
                float z0 = l0 * __expf(l0);
                float z1 = l1 * __expf(l1);
                mv = fmaxf(mv, fmaxf(l0, l1));
                sv += fabsf(z0) + fabsf(z1);
                __stcs(reinterpret_cast<__half2*>(zr + g * 8),
                       __halves2half2(__float2half_rn(z0), __float2half_rn(z1)));
            }
            m2[h] = mv; s2[h] = sv;
        }

        __syncthreads();   // all warps done reading buffer (c&1)
        if (c + 2 < 8 && tid == 0) {
            uint32_t mb = (c & 1) ? mb1 : mb0;
            mbar_expect_tx(mb, CHUNK_BYTES);
            bulk_copy_g2s(bb, qsw + (size_t)(c + 2) * 64 * 256, CHUNK_BYTES, mb);
        }
    }

    // ---- (m,s): reduce across quad (j) then across the 2 n-warps via smem ----
#pragma unroll
    for (int h = 0; h < 2; h++) {
#pragma unroll
        for (int off = 1; off <= 2; off <<= 1) {
            m2[h] = fmaxf(m2[h], __shfl_xor_sync(0xFFFFFFFFu, m2[h], off));
            s2[h] += __shfl_xor_sync(0xFFFFFFFFu, s2[h], off);
        }
    }
    float2* red = reinterpret_cast<float2*>(smem);   // 2KB, B buffers dead now
    __syncthreads();
    if ((lane & 3) == 0) {
#pragma unroll
        for (int h = 0; h < 2; h++) {
            int u_local = warp_m * 16 + h * 8 + (lane >> 2);
            red[warp_n * 128 + u_local] = make_float2(m2[h], s2[h]);
        }
    }
    __syncthreads();
    if (tid < 128) {
        float2 p0 = red[tid];
        float2 p1 = red[128 + tid];
        float mv = fmaxf(p0.x, p1.x);
        float sv = p0.y + p1.y;
        int u = uh * 128 + tid;
        int vi = (b * KK + i) * TT + u;
        g_w[vi] = g_v[vi] / (sv + __expf(mv));
    }
}

// ---------------- combine: out_pre[b,j,u] = sum_i w[b,i,u] * z[b,i,u,j] ----------------
__global__ void __launch_bounds__(256) combine_kernel() {
    __shared__ float ws[KK];
    int u = blockIdx.x, b = blockIdx.y;
    int tid = threadIdx.x;
    for (int ii = tid; ii < KK; ii += 256)
        ws[ii] = g_w[(b * KK + ii) * TT + u];
    __syncthreads();

    const __half2* zp = reinterpret_cast<const __half2*>(g_z)
                        + ((size_t)(b * KK * TT + u)) * (QQ / 2) + tid;
    float accx = 0.f, accy = 0.f;
#pragma unroll 8
    for (int i = 0; i < KK; i++) {
        __half2 zz = __ldcs(zp);
        float2 zf = __half22float2(zz);
        float wv = ws[i];
        accx += wv * zf.x;
        accy += wv * zf.y;
        zp += (size_t)TT * (QQ / 2);
    }
    int j = tid * 2;
    g_opre[(b * QQ + j) * TT + u]     = accx;
    g_opre[(b * QQ + j + 1) * TT + u] = accy;
}

// ---------------- launch ----------------
extern "C" void kernel_launch(void* const* d_in, const int* in_sizes, int n_in,
                              void* d_out, int out_size) {
    const float* q_t = (const float*)d_in[0];
    const float* k_t = (const float*)d_in[1];
    const float* v_t = (const float*)d_in[2];
    const float* Wk  = (const float*)d_in[3];
    const float* Wq  = (const float*)d_in[4];
    const float* Wva = (const float*)d_in[5];
    const float* Wal = (const float*)d_in[6];
    const float* Wvo = (const float*)d_in[7];
    float* out = (float*)d_out;

    cudaFuncSetAttribute(attn_core, cudaFuncAttributeMaxDynamicSharedMemorySize, S_TOTAL);

    dim3 pg(32, 4);
    proj_kernel<<<pg, 256>>>(k_t, Wk, 0, nullptr);   // g_kproj
    proj_kernel<<<pg, 256>>>(q_t, Wq, 1, nullptr);   // g_qh (pre-swizzled)
    proj_kernel<<<pg, 256>>>(v_t, Wva, 2, nullptr);  // g_v

    attn_core<<<BB * KK * 2, 512, S_TOTAL>>>(Wal);

    combine_kernel<<<dim3(TT, BB), 256>>>();

    proj_kernel<<<pg, 256>>>(nullptr, Wvo, 3, out);  // out = g_opre @ Wvo^T
}